// round 1
// baseline (speedup 1.0000x reference)
#include <cuda_runtime.h>

#define NN 50000
#define EE 1600000
#define GG 256
#define HH 64
#define DD 96
#define OUTC 10
#define SCAN_B 49          // ceil(NN/1024)
#define NCHUNK 3125        // 50000 / 16 nodes per chunk

// ---------------- device scratch (no allocs allowed) ----------------
__device__ int g_cnt_row[NN], g_cnt_col[NN];
__device__ int g_off_row[NN], g_off_col[NN];
__device__ int g_cur_row[NN], g_cur_col[NN];
__device__ int g_bsum[2 * SCAN_B];
__device__ int g_csr_row_eid[EE];   // edge ids sorted by source (row)
__device__ int g_csr_col_src[EE];   // source node ids sorted by target (col)
__device__ float g_xc[NN * DD];     // concat(x, edge_aggr)
__device__ float g_agg[NN * DD];    // neighbor-summed xc
__device__ float g_xout[NN * HH];   // layer output
__device__ float g_pooled[GG * HH];

// ---------------- CSR construction ----------------
__global__ void zero_k() {
    int i = blockIdx.x * blockDim.x + threadIdx.x;
    if (i < NN) { g_cnt_row[i] = 0; g_cnt_col[i] = 0; }
    if (i < GG * HH) g_pooled[i] = 0.f;
}

__global__ void count_k(const int* __restrict__ ei) {
    int e = blockIdx.x * blockDim.x + threadIdx.x;
    if (e < EE) {
        atomicAdd(&g_cnt_row[ei[e]], 1);
        atomicAdd(&g_cnt_col[ei[EE + e]], 1);
    }
}

__global__ void scan_p1() {
    __shared__ int s[1024];
    int arr = blockIdx.x / SCAN_B;
    int blk = blockIdx.x % SCAN_B;
    int i = blk * 1024 + threadIdx.x;
    const int* cnt = arr ? g_cnt_col : g_cnt_row;
    int* off = arr ? g_off_col : g_off_row;
    int v = (i < NN) ? cnt[i] : 0;
    s[threadIdx.x] = v;
    __syncthreads();
    for (int d = 1; d < 1024; d <<= 1) {
        int t = (threadIdx.x >= d) ? s[threadIdx.x - d] : 0;
        __syncthreads();
        s[threadIdx.x] += t;
        __syncthreads();
    }
    if (i < NN) off[i] = s[threadIdx.x] - v;     // local exclusive
    if (threadIdx.x == 1023) g_bsum[blockIdx.x] = s[1023];
}

__global__ void scan_p2() {
    int a = threadIdx.x;
    if (a < 2) {
        int run = 0;
        for (int b = 0; b < SCAN_B; b++) {
            int t = g_bsum[a * SCAN_B + b];
            g_bsum[a * SCAN_B + b] = run;
            run += t;
        }
    }
}

__global__ void scan_p3() {
    int i = blockIdx.x * blockDim.x + threadIdx.x;
    if (i < NN) {
        int o = g_off_row[i] + g_bsum[i >> 10];
        g_off_row[i] = o; g_cur_row[i] = o;
    } else if (i < 2 * NN) {
        int idx = i - NN;
        int o = g_off_col[idx] + g_bsum[SCAN_B + (idx >> 10)];
        g_off_col[idx] = o; g_cur_col[idx] = o;
    }
}

__global__ void fill_k(const int* __restrict__ ei) {
    int e = blockIdx.x * blockDim.x + threadIdx.x;
    if (e < EE) {
        int r = ei[e], c = ei[EE + e];
        int p = atomicAdd(&g_cur_row[r], 1);
        g_csr_row_eid[p] = e;
        int q = atomicAdd(&g_cur_col[c], 1);
        g_csr_col_src[q] = r;
    }
}

// ---------------- per-layer kernels ----------------
// xc[n] = [ xprev[n] (64) | sum_{e: row[e]==n} edge_attr[e] (32) ]
__global__ void build_xc_k(const float* __restrict__ x0,
                           const float* __restrict__ ea, int layer) {
    int w = (blockIdx.x * blockDim.x + threadIdx.x) >> 5;
    int lane = threadIdx.x & 31;
    if (w >= NN) return;
    const float* xprev = layer ? g_xout : x0;
    float* out = &g_xc[w * DD];
    out[lane]      = xprev[w * HH + lane];
    out[32 + lane] = xprev[w * HH + 32 + lane];
    int s = g_off_row[w], c = g_cnt_row[w];
    float acc = 0.f;
    for (int k = 0; k < c; k++) {
        int eid = g_csr_row_eid[s + k];
        acc += ea[eid * 32 + lane];
    }
    out[64 + lane] = acc;
}

// agg[n] = sum_{e: col[e]==n} xc[row[e]]
__global__ void gather_k() {
    int w = (blockIdx.x * blockDim.x + threadIdx.x) >> 5;
    int lane = threadIdx.x & 31;
    if (w >= NN) return;
    int s = g_off_col[w], c = g_cnt_col[w];
    float a0 = 0.f, a1 = 0.f, a2 = 0.f;
    for (int k = 0; k < c; k++) {
        int src = g_csr_col_src[s + k];
        const float* xr = &g_xc[src * DD];
        a0 += xr[lane];
        a1 += xr[32 + lane];
        a2 += xr[64 + lane];
    }
    float* o = &g_agg[w * DD];
    o[lane] = a0; o[32 + lane] = a1; o[64 + lane] = a2;
}

// ---------------- fused dual-MLP: xout = relu(rel(agg) + root(xc)) ----------------
#define O_W1R 0
#define O_W1O 6144
#define O_W2R 12288
#define O_W2O 16384
#define O_B1R 20480
#define O_B1O 20544
#define O_B2S 20608
#define O_INA 20736
#define O_INX 22272
#define O_HR  23808
#define O_HO  24832
#define SMEM_FLOATS 25856
#define MLP_SMEM (SMEM_FLOATS * 4)

__global__ void mlp_k(const float* __restrict__ W1r, const float* __restrict__ b1r,
                      const float* __restrict__ W2r, const float* __restrict__ b2r,
                      const float* __restrict__ W1o, const float* __restrict__ b1o,
                      const float* __restrict__ W2o, const float* __restrict__ b2o) {
    extern __shared__ float sm[];
    int tid = threadIdx.x;
    for (int i = tid; i < 6144; i += 256) { sm[O_W1R + i] = W1r[i]; sm[O_W1O + i] = W1o[i]; }
    for (int i = tid; i < 4096; i += 256) { sm[O_W2R + i] = W2r[i]; sm[O_W2O + i] = W2o[i]; }
    if (tid < 64) {
        sm[O_B1R + tid] = b1r[tid];
        sm[O_B1O + tid] = b1o[tid];
        sm[O_B2S + tid] = b2r[tid] + b2o[tid];
    }
    __syncthreads();
    int j = tid & 63, grp = tid >> 6;   // 4 groups x 4 node-slots = 16 nodes/chunk
    for (int chunk = blockIdx.x; chunk < NCHUNK; chunk += gridDim.x) {
        int base = chunk * 16;
        for (int idx = tid; idx < 16 * 96; idx += 256) {
            int nd = idx / 96, k = idx - nd * 96;
            int g = nd >> 2, sl = nd & 3;
            sm[O_INA + (g * 96 + k) * 4 + sl] = g_agg[(base + nd) * 96 + k];
            sm[O_INX + (g * 96 + k) * 4 + sl] = g_xc[(base + nd) * 96 + k];
        }
        __syncthreads();
        float hr0 = sm[O_B1R + j], hr1 = hr0, hr2 = hr0, hr3 = hr0;
        float ho0 = sm[O_B1O + j], ho1 = ho0, ho2 = ho0, ho3 = ho0;
        const float* pa = &sm[O_INA + grp * 96 * 4];
        const float* px = &sm[O_INX + grp * 96 * 4];
        #pragma unroll 8
        for (int k = 0; k < 96; k++) {
            float wr = sm[O_W1R + k * 64 + j];
            float wo = sm[O_W1O + k * 64 + j];
            float4 a = *(const float4*)&pa[k * 4];
            float4 x = *(const float4*)&px[k * 4];
            hr0 = fmaf(a.x, wr, hr0); hr1 = fmaf(a.y, wr, hr1);
            hr2 = fmaf(a.z, wr, hr2); hr3 = fmaf(a.w, wr, hr3);
            ho0 = fmaf(x.x, wo, ho0); ho1 = fmaf(x.y, wo, ho1);
            ho2 = fmaf(x.z, wo, ho2); ho3 = fmaf(x.w, wo, ho3);
        }
        hr0 = fmaxf(hr0, 0.f); hr1 = fmaxf(hr1, 0.f); hr2 = fmaxf(hr2, 0.f); hr3 = fmaxf(hr3, 0.f);
        ho0 = fmaxf(ho0, 0.f); ho1 = fmaxf(ho1, 0.f); ho2 = fmaxf(ho2, 0.f); ho3 = fmaxf(ho3, 0.f);
        *(float4*)&sm[O_HR + (grp * 64 + j) * 4] = make_float4(hr0, hr1, hr2, hr3);
        *(float4*)&sm[O_HO + (grp * 64 + j) * 4] = make_float4(ho0, ho1, ho2, ho3);
        __syncthreads();
        float o0 = sm[O_B2S + j], o1 = o0, o2 = o0, o3 = o0;
        const float* ph = &sm[O_HR + grp * 64 * 4];
        const float* pg = &sm[O_HO + grp * 64 * 4];
        #pragma unroll 8
        for (int k = 0; k < 64; k++) {
            float wr = sm[O_W2R + k * 64 + j];
            float wo = sm[O_W2O + k * 64 + j];
            float4 h = *(const float4*)&ph[k * 4];
            float4 g = *(const float4*)&pg[k * 4];
            o0 = fmaf(h.x, wr, o0); o1 = fmaf(h.y, wr, o1);
            o2 = fmaf(h.z, wr, o2); o3 = fmaf(h.w, wr, o3);
            o0 = fmaf(g.x, wo, o0); o1 = fmaf(g.y, wo, o1);
            o2 = fmaf(g.z, wo, o2); o3 = fmaf(g.w, wo, o3);
        }
        int nb = base + grp * 4;
        g_xout[(nb + 0) * 64 + j] = fmaxf(o0, 0.f);
        g_xout[(nb + 1) * 64 + j] = fmaxf(o1, 0.f);
        g_xout[(nb + 2) * 64 + j] = fmaxf(o2, 0.f);
        g_xout[(nb + 3) * 64 + j] = fmaxf(o3, 0.f);
        __syncthreads();
    }
}

// ---------------- pooling + final MLP ----------------
__global__ void pool_k(const int* __restrict__ batch) {
    int i = blockIdx.x * blockDim.x + threadIdx.x;
    if (i < NN * HH) {
        int n = i >> 6, c = i & 63;
        atomicAdd(&g_pooled[batch[n] * HH + c], g_xout[i]);
    }
}

__global__ void fin_k(const float* __restrict__ W1, const float* __restrict__ b1,
                      const float* __restrict__ W2, const float* __restrict__ b2,
                      float* __restrict__ out) {
    __shared__ float p[64], h[64];
    int g = blockIdx.x, t = threadIdx.x;
    p[t] = g_pooled[g * 64 + t];
    __syncthreads();
    float a = b1[t];
    #pragma unroll
    for (int k = 0; k < 64; k++) a = fmaf(p[k], W1[k * 64 + t], a);
    h[t] = fmaxf(a, 0.f);
    __syncthreads();
    if (t < OUTC) {
        float o = b2[t];
        #pragma unroll
        for (int k = 0; k < 64; k++) o = fmaf(h[k], W2[k * OUTC + t], o);
        out[g * OUTC + t] = o;
    }
}

// ---------------- launch ----------------
extern "C" void kernel_launch(void* const* d_in, const int* in_sizes, int n_in,
                              void* d_out, int out_size) {
    const float* x  = (const float*)d_in[0];
    const float* ea = (const float*)d_in[1];
    // per layer: rel_W1, rel_b1, rel_W2, rel_b2, root_W1, root_b1, root_W2, root_b2
    const float* L[2][8];
    for (int l = 0; l < 2; l++)
        for (int i = 0; i < 8; i++)
            L[l][i] = (const float*)d_in[2 + l * 8 + i];
    const float* finW1 = (const float*)d_in[18];
    const float* finb1 = (const float*)d_in[19];
    const float* finW2 = (const float*)d_in[20];
    const float* finb2 = (const float*)d_in[21];
    const int* ei    = (const int*)d_in[22];
    const int* batch = (const int*)d_in[23];
    float* out = (float*)d_out;

    cudaFuncSetAttribute(mlp_k, cudaFuncAttributeMaxDynamicSharedMemorySize, MLP_SMEM);

    zero_k<<<(NN + 255) / 256, 256>>>();
    count_k<<<(EE + 255) / 256, 256>>>(ei);
    scan_p1<<<2 * SCAN_B, 1024>>>();
    scan_p2<<<1, 32>>>();
    scan_p3<<<(2 * NN + 255) / 256, 256>>>();
    fill_k<<<(EE + 255) / 256, 256>>>(ei);

    for (int l = 0; l < 2; l++) {
        build_xc_k<<<6250, 256>>>(x, ea, l);
        gather_k<<<6250, 256>>>();
        mlp_k<<<592, 256, MLP_SMEM>>>(L[l][0], L[l][1], L[l][2], L[l][3],
                                      L[l][4], L[l][5], L[l][6], L[l][7]);
    }
    pool_k<<<(NN * HH + 255) / 256, 256>>>(batch);
    fin_k<<<GG, 64>>>(finW1, finb1, finW2, finb2, out);
}